// round 1
// baseline (speedup 1.0000x reference)
#include <cuda_runtime.h>
#include <math.h>

// Problem shapes (fixed)
#define BB 32
#define NN 1024
#define CC 512
#define LL 512
// GEMM tiling
#define TM 64
#define TN 64
#define TK 16

// Scratch (allocation-free rule: __device__ globals)
__device__ float g_Q[(size_t)BB * NN * LL];   // 64 MB, q already scaled
__device__ float g_K[(size_t)BB * NN * LL];   // 64 MB
__device__ float g_S[(size_t)BB * NN * NN];   // 128 MB, scores -> probs in place

// ---------------------------------------------------------------------------
// Kernel 1: projection. C[m, n] = sum_c x[m, c] * W[n, c] + b[n]
// m in [0, B*N), n in [0, 2L). n < L -> Q (scaled), n >= L -> K.
// NT GEMM: both operands row-major with K (=C) innermost.
// ---------------------------------------------------------------------------
__global__ __launch_bounds__(256) void proj_kernel(const float* __restrict__ x,
                                                   const float* __restrict__ W,
                                                   const float* __restrict__ bias)
{
    __shared__ float As[TK][TM];
    __shared__ float Bs[TK][TN];

    const int tid = threadIdx.x;
    const int tx = tid & 15;
    const int ty = tid >> 4;
    const int m0 = blockIdx.y * TM;
    const int n0 = blockIdx.x * TN;

    const int lrow = tid >> 2;        // 0..63
    const int lk4  = (tid & 3) * 4;   // 0,4,8,12

    float acc[4][4] = {};

    for (int k0 = 0; k0 < CC; k0 += TK) {
        float4 a = *(const float4*)&x[(size_t)(m0 + lrow) * CC + k0 + lk4];
        float4 b = *(const float4*)&W[(size_t)(n0 + lrow) * CC + k0 + lk4];
        As[lk4 + 0][lrow] = a.x; As[lk4 + 1][lrow] = a.y;
        As[lk4 + 2][lrow] = a.z; As[lk4 + 3][lrow] = a.w;
        Bs[lk4 + 0][lrow] = b.x; Bs[lk4 + 1][lrow] = b.y;
        Bs[lk4 + 2][lrow] = b.z; Bs[lk4 + 3][lrow] = b.w;
        __syncthreads();
#pragma unroll
        for (int kk = 0; kk < TK; kk++) {
            float4 ar = *(const float4*)&As[kk][ty * 4];
            float4 br = *(const float4*)&Bs[kk][tx * 4];
            float arf[4] = {ar.x, ar.y, ar.z, ar.w};
            float brf[4] = {br.x, br.y, br.z, br.w};
#pragma unroll
            for (int u = 0; u < 4; u++)
#pragma unroll
                for (int v = 0; v < 4; v++)
                    acc[u][v] += arf[u] * brf[v];
        }
        __syncthreads();
    }

    const float scale = rsqrtf((float)LL);
    const bool is_q = (n0 < LL);   // block-uniform (TN divides LL)
#pragma unroll
    for (int u = 0; u < 4; u++) {
        const int m = m0 + ty * 4 + u;
#pragma unroll
        for (int v = 0; v < 4; v++) {
            const int n = n0 + tx * 4 + v;
            float val = acc[u][v] + bias[n];
            if (is_q)
                g_Q[(size_t)m * LL + n] = val * scale;
            else
                g_K[(size_t)m * LL + (n - LL)] = val;
        }
    }
}

// ---------------------------------------------------------------------------
// Kernel 2: scores. S[b, n, m] = sum_l Q[b, n, l] * K[b, m, l]  (NT GEMM)
// blockIdx.z = batch, blockIdx.y -> n-tile, blockIdx.x -> m-tile
// ---------------------------------------------------------------------------
__global__ __launch_bounds__(256) void score_kernel()
{
    __shared__ float As[TK][TM];
    __shared__ float Bs[TK][TN];

    const int tid = threadIdx.x;
    const int tx = tid & 15;
    const int ty = tid >> 4;
    const int b  = blockIdx.z;
    const int n0t = blockIdx.y * TM;   // n tile (rows)
    const int m0t = blockIdx.x * TN;   // m tile (cols)

    const float* Qb = g_Q + (size_t)b * NN * LL;
    const float* Kb = g_K + (size_t)b * NN * LL;
    float* Sb = g_S + (size_t)b * NN * NN;

    const int lrow = tid >> 2;
    const int lk4  = (tid & 3) * 4;

    float acc[4][4] = {};

    for (int k0 = 0; k0 < LL; k0 += TK) {
        float4 a = *(const float4*)&Qb[(size_t)(n0t + lrow) * LL + k0 + lk4];
        float4 c = *(const float4*)&Kb[(size_t)(m0t + lrow) * LL + k0 + lk4];
        As[lk4 + 0][lrow] = a.x; As[lk4 + 1][lrow] = a.y;
        As[lk4 + 2][lrow] = a.z; As[lk4 + 3][lrow] = a.w;
        Bs[lk4 + 0][lrow] = c.x; Bs[lk4 + 1][lrow] = c.y;
        Bs[lk4 + 2][lrow] = c.z; Bs[lk4 + 3][lrow] = c.w;
        __syncthreads();
#pragma unroll
        for (int kk = 0; kk < TK; kk++) {
            float4 ar = *(const float4*)&As[kk][ty * 4];
            float4 br = *(const float4*)&Bs[kk][tx * 4];
            float arf[4] = {ar.x, ar.y, ar.z, ar.w};
            float brf[4] = {br.x, br.y, br.z, br.w};
#pragma unroll
            for (int u = 0; u < 4; u++)
#pragma unroll
                for (int v = 0; v < 4; v++)
                    acc[u][v] += arf[u] * brf[v];
        }
        __syncthreads();
    }

#pragma unroll
    for (int u = 0; u < 4; u++) {
        const int n = n0t + ty * 4 + u;
#pragma unroll
        for (int v = 0; v < 4; v++) {
            const int m = m0t + tx * 4 + v;
            Sb[(size_t)n * NN + m] = acc[u][v];
        }
    }
}

// ---------------------------------------------------------------------------
// Kernel 3: row softmax in place on S. One block per row (B*N rows of len N).
// ---------------------------------------------------------------------------
__global__ __launch_bounds__(256) void softmax_kernel()
{
    const size_t row = blockIdx.x;
    float* S = g_S + row * NN;
    const int tid = threadIdx.x;

    float4* S4 = (float4*)S;
    float4 v = S4[tid];   // 256 threads x float4 = 1024 elements

    // max reduce
    float mx = fmaxf(fmaxf(v.x, v.y), fmaxf(v.z, v.w));
#pragma unroll
    for (int o = 16; o > 0; o >>= 1)
        mx = fmaxf(mx, __shfl_xor_sync(0xffffffffu, mx, o));
    __shared__ float red[8];
    if ((tid & 31) == 0) red[tid >> 5] = mx;
    __syncthreads();
    if (tid < 8) {
        float t = red[tid];
#pragma unroll
        for (int o = 4; o > 0; o >>= 1)
            t = fmaxf(t, __shfl_xor_sync(0xffu, t, o));
        if (tid == 0) red[0] = t;
    }
    __syncthreads();
    mx = red[0];
    __syncthreads();

    // exp + sum
    v.x = __expf(v.x - mx); v.y = __expf(v.y - mx);
    v.z = __expf(v.z - mx); v.w = __expf(v.w - mx);
    float sm = v.x + v.y + v.z + v.w;
#pragma unroll
    for (int o = 16; o > 0; o >>= 1)
        sm += __shfl_xor_sync(0xffffffffu, sm, o);
    if ((tid & 31) == 0) red[tid >> 5] = sm;
    __syncthreads();
    if (tid < 8) {
        float t = red[tid];
#pragma unroll
        for (int o = 4; o > 0; o >>= 1)
            t += __shfl_xor_sync(0xffu, t, o);
        if (tid == 0) red[0] = t;
    }
    __syncthreads();
    const float inv = 1.0f / red[0];

    v.x *= inv; v.y *= inv; v.z *= inv; v.w *= inv;
    S4[tid] = v;
}

// ---------------------------------------------------------------------------
// Kernel 4: out[b, n, c] = sum_m P[b, n, m] * y[b, m, c]   (NN GEMM)
// blockIdx.z = batch, blockIdx.y -> n-tile (M dim), blockIdx.x -> c-tile (N dim)
// ---------------------------------------------------------------------------
__global__ __launch_bounds__(256) void out_kernel(const float* __restrict__ y,
                                                  float* __restrict__ out)
{
    __shared__ float As[TK][TM];
    __shared__ float Bs[TK][TN];

    const int tid = threadIdx.x;
    const int tx = tid & 15;
    const int ty = tid >> 4;
    const int b  = blockIdx.z;
    const int n0t = blockIdx.y * TM;   // output row tile (n)
    const int c0t = blockIdx.x * TN;   // output col tile (c)

    const float* Pb = g_S + (size_t)b * NN * NN;
    const float* Yb = y + (size_t)b * NN * CC;
    float* Ob = out + (size_t)b * NN * CC;

    // A tile load indices (64 rows x 16 k)
    const int lrow = tid >> 2;
    const int lk4  = (tid & 3) * 4;
    // B tile load indices (16 k x 64 cols)
    const int bk  = tid >> 4;          // 0..15
    const int bj4 = (tid & 15) * 4;    // 0..60

    float acc[4][4] = {};

    for (int k0 = 0; k0 < NN; k0 += TK) {
        float4 a = *(const float4*)&Pb[(size_t)(n0t + lrow) * NN + k0 + lk4];
        float4 c = *(const float4*)&Yb[(size_t)(k0 + bk) * CC + c0t + bj4];
        As[lk4 + 0][lrow] = a.x; As[lk4 + 1][lrow] = a.y;
        As[lk4 + 2][lrow] = a.z; As[lk4 + 3][lrow] = a.w;
        *(float4*)&Bs[bk][bj4] = c;
        __syncthreads();
#pragma unroll
        for (int kk = 0; kk < TK; kk++) {
            float4 ar = *(const float4*)&As[kk][ty * 4];
            float4 br = *(const float4*)&Bs[kk][tx * 4];
            float arf[4] = {ar.x, ar.y, ar.z, ar.w};
            float brf[4] = {br.x, br.y, br.z, br.w};
#pragma unroll
            for (int u = 0; u < 4; u++)
#pragma unroll
                for (int v = 0; v < 4; v++)
                    acc[u][v] += arf[u] * brf[v];
        }
        __syncthreads();
    }

#pragma unroll
    for (int u = 0; u < 4; u++) {
        const int n = n0t + ty * 4 + u;
#pragma unroll
        for (int v = 0; v < 4; v++) {
            const int c = c0t + tx * 4 + v;
            Ob[(size_t)n * CC + c] = acc[u][v];
        }
    }
}

// ---------------------------------------------------------------------------
extern "C" void kernel_launch(void* const* d_in, const int* in_sizes, int n_in,
                              void* d_out, int out_size)
{
    const float* x    = (const float*)d_in[0];
    const float* y    = (const float*)d_in[1];
    const float* W_qk = (const float*)d_in[2];
    const float* b_qk = (const float*)d_in[3];
    float* out = (float*)d_out;

    (void)in_sizes; (void)n_in; (void)out_size;

    // 1) projection: M = B*N = 32768, Nout = 2L = 1024
    {
        dim3 grid(2 * LL / TN, (BB * NN) / TM, 1);   // (16, 512)
        proj_kernel<<<grid, 256>>>(x, W_qk, b_qk);
    }
    // 2) scores: per batch 1024 x 1024
    {
        dim3 grid(NN / TN, NN / TM, BB);             // (16, 16, 32)
        score_kernel<<<grid, 256>>>();
    }
    // 3) softmax over rows
    {
        softmax_kernel<<<BB * NN, 256>>>();
    }
    // 4) out: per batch 1024 x 512
    {
        dim3 grid(CC / TN, NN / TM, BB);             // (8, 16, 32)
        out_kernel<<<grid, 256>>>(y, out);
    }
}

// round 2
// speedup vs baseline: 3.2779x; 3.2779x over previous
#include <cuda_runtime.h>
#include <math.h>
#include <stdint.h>

// Problem shapes (fixed)
#define B_ 32
#define N_ 1024
#define C_ 512
#define L_ 512

// Scratch (allocation-free rule: __device__ globals)
__device__ float g_Q[(size_t)B_ * N_ * L_];   // 64 MB, q already scaled
__device__ float g_K[(size_t)B_ * N_ * L_];   // 64 MB
__device__ float g_S[(size_t)B_ * N_ * N_];   // 128 MB, scores -> probs in place

// ---------------------------------------------------------------------------
// TF32 helpers
// ---------------------------------------------------------------------------
__device__ __forceinline__ uint32_t f2tf(float f) {
    uint32_t u;
    asm("cvt.rna.tf32.f32 %0, %1;" : "=r"(u) : "f"(f));
    return u;
}

__device__ __forceinline__ void mma_tf32(float c[4],
                                         uint32_t a0, uint32_t a1, uint32_t a2, uint32_t a3,
                                         uint32_t b0, uint32_t b1) {
    asm volatile(
        "mma.sync.aligned.m16n8k8.row.col.f32.tf32.tf32.f32 "
        "{%0,%1,%2,%3}, {%4,%5,%6,%7}, {%8,%9}, {%0,%1,%2,%3};"
        : "+f"(c[0]), "+f"(c[1]), "+f"(c[2]), "+f"(c[3])
        : "r"(a0), "r"(a1), "r"(a2), "r"(a3), "r"(b0), "r"(b1));
}

// ---------------------------------------------------------------------------
// Unified TF32 GEMM.
// MODE 0: proj   C[m,n]= x[m,:]·W[n,:]   M=32768 N=1024 K=512 (NT), epi: bias+scale -> g_Q/g_K
// MODE 1: score  S[b,n,m]= Q[b,n,:]·K[b,m,:]  M=N=1024 K=512 per batch (NT)
// MODE 2: out    O[b,n,c]= P[b,n,:]·Y[b,:,c]  M=1024 N=512 K=1024 per batch (NN)
//
// Block tile 128x128, BK=16, 256 threads (8 warps, 2x4), warp tile 64x32.
// ---------------------------------------------------------------------------
template <int MODE>
__global__ __launch_bounds__(256) void mma_gemm(const float* __restrict__ Ag,
                                                const float* __restrict__ Bg,
                                                float* __restrict__ Cg,
                                                const float* __restrict__ bias)
{
    constexpr int Kd  = (MODE == 2) ? 1024 : 512;
    constexpr int lda = (MODE == 2) ? 1024 : 512;
    constexpr int ldb = 512;

    // Smem: As[m][k] pad-20 ; Bs NT: [n][k] pad-20 ; Bs NN: [k][n] pad-136
    __shared__ uint32_t As[128 * 20];
    __shared__ uint32_t Bs[2560];

    const int tid  = threadIdx.x;
    const int lane = tid & 31;
    const int wid  = tid >> 5;
    const int wm   = wid >> 2;   // 0..1
    const int wn   = wid & 3;    // 0..3
    const int gid  = lane >> 2;  // 0..7
    const int tig  = lane & 3;   // 0..3

    const int m0 = blockIdx.y * 128;
    const int n0 = blockIdx.x * 128;
    const int z  = blockIdx.z;

    const float* A;
    const float* Bp;
    if (MODE == 0) { A = Ag;                          Bp = Bg; }
    if (MODE == 1) { A = g_Q + (size_t)z * N_ * L_;   Bp = g_K + (size_t)z * N_ * L_; }
    if (MODE == 2) { A = g_S + (size_t)z * N_ * N_;   Bp = Bg + (size_t)z * N_ * C_; }

    float acc[4][4][4] = {};

    for (int k0 = 0; k0 < Kd; k0 += 16) {
        // ---- stage A tile: 128 rows x 16 k (convert to tf32 on the way) ----
#pragma unroll
        for (int i = 0; i < 2; i++) {
            const int lin = tid + i * 256;           // 0..511
            const int r   = lin >> 2;                // 0..127
            const int k4  = (lin & 3) * 4;           // 0,4,8,12
            float4 v = *(const float4*)&A[(size_t)(m0 + r) * lda + k0 + k4];
            uint32_t* d = &As[r * 20 + k4];
            d[0] = f2tf(v.x); d[1] = f2tf(v.y); d[2] = f2tf(v.z); d[3] = f2tf(v.w);
        }
        // ---- stage B tile ----
        if (MODE < 2) {
            // NT: B rows are n, k contiguous -> Bs[n][k] pad 20
#pragma unroll
            for (int i = 0; i < 2; i++) {
                const int lin = tid + i * 256;
                const int r   = lin >> 2;            // n 0..127
                const int k4  = (lin & 3) * 4;
                float4 v = *(const float4*)&Bp[(size_t)(n0 + r) * ldb + k0 + k4];
                uint32_t* d = &Bs[r * 20 + k4];
                d[0] = f2tf(v.x); d[1] = f2tf(v.y); d[2] = f2tf(v.z); d[3] = f2tf(v.w);
            }
        } else {
            // NN: B rows are k, n contiguous -> Bs[k][n] pad 136
#pragma unroll
            for (int i = 0; i < 2; i++) {
                const int lin = tid + i * 256;       // 0..511
                const int kk  = lin >> 5;            // 0..15
                const int n4  = (lin & 31) * 4;      // 0..124
                float4 v = *(const float4*)&Bp[(size_t)(k0 + kk) * ldb + n0 + n4];
                uint32_t* d = &Bs[kk * 136 + n4];
                d[0] = f2tf(v.x); d[1] = f2tf(v.y); d[2] = f2tf(v.z); d[3] = f2tf(v.w);
            }
        }
        __syncthreads();

        // ---- two k8 steps ----
#pragma unroll
        for (int ks = 0; ks < 2; ks++) {
            const int kb = ks * 8;
            uint32_t af[4][4];
#pragma unroll
            for (int mi = 0; mi < 4; mi++) {
                const int mr = wm * 64 + mi * 16 + gid;
                af[mi][0] = As[mr * 20 + kb + tig];
                af[mi][1] = As[(mr + 8) * 20 + kb + tig];
                af[mi][2] = As[mr * 20 + kb + tig + 4];
                af[mi][3] = As[(mr + 8) * 20 + kb + tig + 4];
            }
            uint32_t bf[4][2];
#pragma unroll
            for (int ni = 0; ni < 4; ni++) {
                const int nc = wn * 32 + ni * 8 + gid;
                if (MODE < 2) {
                    bf[ni][0] = Bs[nc * 20 + kb + tig];
                    bf[ni][1] = Bs[nc * 20 + kb + tig + 4];
                } else {
                    bf[ni][0] = Bs[(kb + tig) * 136 + nc];
                    bf[ni][1] = Bs[(kb + tig + 4) * 136 + nc];
                }
            }
#pragma unroll
            for (int mi = 0; mi < 4; mi++)
#pragma unroll
                for (int ni = 0; ni < 4; ni++)
                    mma_tf32(acc[mi][ni], af[mi][0], af[mi][1], af[mi][2], af[mi][3],
                             bf[ni][0], bf[ni][1]);
        }
        __syncthreads();
    }

    // ---- epilogue ----
    const float scale = rsqrtf((float)L_);
#pragma unroll
    for (int mi = 0; mi < 4; mi++) {
#pragma unroll
        for (int ni = 0; ni < 4; ni++) {
            const int m = m0 + wm * 64 + mi * 16 + gid;
            const int n = n0 + wn * 32 + ni * 8 + tig * 2;
            float c0 = acc[mi][ni][0], c1 = acc[mi][ni][1];
            float c2 = acc[mi][ni][2], c3 = acc[mi][ni][3];
            if (MODE == 0) {
                const float b0v = bias[n], b1v = bias[n + 1];
                if (n0 < L_) {  // whole block is Q (n0 is a multiple of 128)
                    float2 p0 = make_float2((c0 + b0v) * scale, (c1 + b1v) * scale);
                    float2 p1 = make_float2((c2 + b0v) * scale, (c3 + b1v) * scale);
                    *(float2*)&g_Q[(size_t)m * L_ + n]       = p0;
                    *(float2*)&g_Q[(size_t)(m + 8) * L_ + n] = p1;
                } else {
                    const int nk = n - L_;
                    float2 p0 = make_float2(c0 + b0v, c1 + b1v);
                    float2 p1 = make_float2(c2 + b0v, c3 + b1v);
                    *(float2*)&g_K[(size_t)m * L_ + nk]       = p0;
                    *(float2*)&g_K[(size_t)(m + 8) * L_ + nk] = p1;
                }
            } else if (MODE == 1) {
                float* Sb = g_S + (size_t)z * N_ * N_;
                *(float2*)&Sb[(size_t)m * N_ + n]       = make_float2(c0, c1);
                *(float2*)&Sb[(size_t)(m + 8) * N_ + n] = make_float2(c2, c3);
            } else {
                float* Ob = Cg + (size_t)z * N_ * C_;
                *(float2*)&Ob[(size_t)m * C_ + n]       = make_float2(c0, c1);
                *(float2*)&Ob[(size_t)(m + 8) * C_ + n] = make_float2(c2, c3);
            }
        }
    }
}

// ---------------------------------------------------------------------------
// Row softmax in place on S. One block per row (B*N rows of len N).
// ---------------------------------------------------------------------------
__global__ __launch_bounds__(256) void softmax_kernel()
{
    const size_t row = blockIdx.x;
    float* S = g_S + row * N_;
    const int tid = threadIdx.x;

    float4* S4 = (float4*)S;
    float4 v = S4[tid];   // 256 threads x float4 = 1024 elements

    float mx = fmaxf(fmaxf(v.x, v.y), fmaxf(v.z, v.w));
#pragma unroll
    for (int o = 16; o > 0; o >>= 1)
        mx = fmaxf(mx, __shfl_xor_sync(0xffffffffu, mx, o));
    __shared__ float red[8];
    if ((tid & 31) == 0) red[tid >> 5] = mx;
    __syncthreads();
    if (tid < 8) {
        float t = red[tid];
#pragma unroll
        for (int o = 4; o > 0; o >>= 1)
            t = fmaxf(t, __shfl_xor_sync(0xffu, t, o));
        if (tid == 0) red[0] = t;
    }
    __syncthreads();
    mx = red[0];
    __syncthreads();

    v.x = __expf(v.x - mx); v.y = __expf(v.y - mx);
    v.z = __expf(v.z - mx); v.w = __expf(v.w - mx);
    float sm = v.x + v.y + v.z + v.w;
#pragma unroll
    for (int o = 16; o > 0; o >>= 1)
        sm += __shfl_xor_sync(0xffffffffu, sm, o);
    if ((tid & 31) == 0) red[tid >> 5] = sm;
    __syncthreads();
    if (tid < 8) {
        float t = red[tid];
#pragma unroll
        for (int o = 4; o > 0; o >>= 1)
            t += __shfl_xor_sync(0xffu, t, o);
        if (tid == 0) red[0] = t;
    }
    __syncthreads();
    const float inv = 1.0f / red[0];

    v.x *= inv; v.y *= inv; v.z *= inv; v.w *= inv;
    S4[tid] = v;
}

// ---------------------------------------------------------------------------
extern "C" void kernel_launch(void* const* d_in, const int* in_sizes, int n_in,
                              void* d_out, int out_size)
{
    const float* x    = (const float*)d_in[0];
    const float* y    = (const float*)d_in[1];
    const float* W_qk = (const float*)d_in[2];
    const float* b_qk = (const float*)d_in[3];
    float* out = (float*)d_out;

    (void)in_sizes; (void)n_in; (void)out_size;

    // 1) projection: M = 32768, N = 1024, K = 512
    {
        dim3 grid(1024 / 128, 32768 / 128, 1);       // (8, 256)
        mma_gemm<0><<<grid, 256>>>(x, W_qk, nullptr, b_qk);
    }
    // 2) scores: per batch 1024 x 1024, K = 512
    {
        dim3 grid(1024 / 128, 1024 / 128, B_);       // (8, 8, 32)
        mma_gemm<1><<<grid, 256>>>(nullptr, nullptr, nullptr, nullptr);
    }
    // 3) softmax over rows
    {
        softmax_kernel<<<B_ * N_, 256>>>();
    }
    // 4) out: per batch 1024 x 512, K = 1024
    {
        dim3 grid(512 / 128, 1024 / 128, B_);        // (4, 8, 32)
        mma_gemm<2><<<grid, 256>>>(nullptr, y, out, nullptr);
    }
}